// round 3
// baseline (speedup 1.0000x reference)
#include <cuda_runtime.h>

#define NS      32768
#define NT      512
#define SEASK   24
#define LEVW    512
#define SEAW    536
#define LOGW    511

#define BLOCK   32
#define CHUNK   8
#define NCHUNK  (NT / CHUNK)   // 64
#define TPAD    12             // tile row stride (floats); 12*L+4q is a perfect bank partition

// Steady-state chunk. POS0 = (8*c) % 24 is a compile-time constant, so all
// seasonal-state indices are static -> the 24-entry buffer lives in registers.
// Within a chunk (8 < 24) every slot is read (value from >=24 steps ago) before
// it is written, and all slots are distinct, so batching reads first is exact.
template<int POS0>
__device__ __forceinline__ void steady_chunk(
    int c, int tid, int s0,
    float a, float oma,
    float& lev, float& llev,
    float (&sbuf)[SEASK],
    float4& ya0, float4& ya1, float4& yb0, float4& yb1,
    const float4*& ynext,
    float* __restrict__ gl, float* __restrict__ gs, float* __restrict__ gd,
    float* __restrict__ ltile, float* __restrict__ stile, float* __restrict__ dtile)
{
    const int t0 = c * CHUNK;

    float yt[CHUNK];
    yt[0] = ya0.x; yt[1] = ya0.y; yt[2] = ya0.z; yt[3] = ya0.w;
    yt[4] = ya1.x; yt[5] = ya1.y; yt[6] = ya1.z; yt[7] = ya1.w;

    // rotate prefetch pipeline (distance 2)
    ya0 = yb0; ya1 = yb1;
    if (c + 2 < NCHUNK) { yb0 = ynext[0]; yb1 = ynext[1]; ynext += 2; }

    float q_[CHUNK], os_[CHUNK], nl_[CHUNK], dt_[CHUNK];

    // independent: first divide batch (MUFU pipelined, register operands)
    #pragma unroll
    for (int k = 0; k < CHUNK; k++) {
        const float sv = sbuf[POS0 + k];
        q_[k]  = a * __fdividef(yt[k], sv);
        os_[k] = oma * sv;
    }
    // the only true carried chain: one FFMA per step
    #pragma unroll
    for (int k = 0; k < CHUNK; k++) { nl_[k] = fmaf(oma, lev, q_[k]); lev = nl_[k]; }
    // independent: season update (second divide batch) into register buffer
    #pragma unroll
    for (int k = 0; k < CHUNK; k++)
        sbuf[POS0 + k] = fmaf(a, __fdividef(yt[k], nl_[k]), os_[k]);
    // independent logs; dt has no carried chain (each uses two adjacent logs)
    #pragma unroll
    for (int k = 0; k < CHUNK; k++) {
        const float ll = __logf(nl_[k]);
        dt_[k] = ll - llev; llev = ll;
    }

    // stage transposed tiles (vector smem stores, conflict-free)
    float4* lt4 = (float4*)(ltile + tid * TPAD);
    float4* st4 = (float4*)(stile + tid * TPAD);
    float4* dt4 = (float4*)(dtile + tid * TPAD);
    lt4[0] = make_float4(nl_[0], nl_[1], nl_[2], nl_[3]);
    lt4[1] = make_float4(nl_[4], nl_[5], nl_[6], nl_[7]);
    st4[0] = make_float4(sbuf[POS0 + 0], sbuf[POS0 + 1], sbuf[POS0 + 2], sbuf[POS0 + 3]);
    st4[1] = make_float4(sbuf[POS0 + 4], sbuf[POS0 + 5], sbuf[POS0 + 6], sbuf[POS0 + 7]);
    dt4[0] = make_float4(dt_[0], dt_[1], dt_[2], dt_[3]);
    dt4[1] = make_float4(dt_[4], dt_[5], dt_[6], dt_[7]);
    __syncwarp();

    // coalesced vector writeback: levels + seasonalities
    #pragma unroll
    for (int j = 0; j < 2; j++) {
        const int fq = tid + 32 * j;
        const int r  = fq >> 1, qd = fq & 1;
        const int grow = s0 + r;
        ((float4*)(gl + (size_t)grow * LEVW + t0))[qd] =
            ((const float4*)(ltile + r * TPAD))[qd];
        ((float4*)(gs + (size_t)grow * SEAW + t0 + SEASK))[qd] =
            ((const float4*)(stile + r * TPAD))[qd];
    }
    // log_diff: row stride 511 is odd -> scalar, but fully coalesced per 8 lanes
    #pragma unroll
    for (int j = 0; j < 8; j++) {
        const int i = tid + 32 * j;
        const int r = i >> 3, k = i & 7;
        gd[(size_t)(s0 + r) * LOGW + t0 - 1 + k] = dtile[r * TPAD + k];
    }
    __syncwarp();
}

__global__ __launch_bounds__(BLOCK) void es_fwd_kernel(
    const float* __restrict__ y,
    const int*   __restrict__ idxs,
    const float* __restrict__ lev_sms_p,
    const float* __restrict__ init_seas_p,
    float* __restrict__ out)
{
    __shared__ __align__(16) float ltile[BLOCK * TPAD];
    __shared__ __align__(16) float stile[BLOCK * TPAD];
    __shared__ __align__(16) float dtile[BLOCK * TPAD];

    const int tid = threadIdx.x;
    const int s0  = blockIdx.x * BLOCK;
    const int s   = s0 + tid;

    float* gl = out;
    float* gs = out + (size_t)NS * LEVW;
    float* gd = gs  + (size_t)NS * SEAW;

    const int idx = idxs[s];
    // reference derives BOTH smoothing params from lev_sms (its own quirk)
    const float a   = 1.0f / (1.0f + __expf(-lev_sms_p[idx]));
    const float oma = 1.0f - a;

    // seasonal state in registers; emit seas cols 0..23
    float sbuf[SEASK];
    {
        const float4* isr = (const float4*)(init_seas_p + (size_t)idx * SEASK);
        float4* gsr = (float4*)(gs + (size_t)s * SEAW);
        #pragma unroll
        for (int qd = 0; qd < 6; qd++) {
            float4 v = isr[qd];
            v.x = __expf(v.x); v.y = __expf(v.y); v.z = __expf(v.z); v.w = __expf(v.w);
            sbuf[4 * qd + 0] = v.x; sbuf[4 * qd + 1] = v.y;
            sbuf[4 * qd + 2] = v.z; sbuf[4 * qd + 3] = v.w;
            gsr[qd] = v;
        }
    }

    // per-thread y row, prefetch pipeline depth 2 (each chunk = one 32B sector)
    const float4* yrow = (const float4*)(y + (size_t)s * NT);
    float4 ya0 = yrow[0], ya1 = yrow[1];
    float4 yb0 = yrow[2], yb1 = yrow[3];
    const float4* ynext = yrow + 4;

    float lev, llev;

    // ---- chunk 0 (peeled: step 0 special, logd starts at t=1) ----
    {
        float yt[CHUNK];
        yt[0] = ya0.x; yt[1] = ya0.y; yt[2] = ya0.z; yt[3] = ya0.w;
        yt[4] = ya1.x; yt[5] = ya1.y; yt[6] = ya1.z; yt[7] = ya1.w;
        ya0 = yb0; ya1 = yb1;
        yb0 = ynext[0]; yb1 = ynext[1]; ynext += 2;

        float q_[CHUNK], os_[CHUNK], nl_[CHUNK], dt_[CHUNK];
        const float st0 = sbuf[0];
        lev  = __fdividef(yt[0], st0);
        llev = __logf(lev);
        nl_[0] = lev; dt_[0] = 0.0f;

        #pragma unroll
        for (int k = 1; k < CHUNK; k++) {
            const float sv = sbuf[k];
            q_[k]  = a * __fdividef(yt[k], sv);
            os_[k] = oma * sv;
        }
        #pragma unroll
        for (int k = 1; k < CHUNK; k++) { nl_[k] = fmaf(oma, lev, q_[k]); lev = nl_[k]; }
        #pragma unroll
        for (int k = 1; k < CHUNK; k++)
            sbuf[k] = fmaf(a, __fdividef(yt[k], nl_[k]), os_[k]);
        #pragma unroll
        for (int k = 1; k < CHUNK; k++) {
            const float ll = __logf(nl_[k]);
            dt_[k] = ll - llev; llev = ll;
        }

        float4* lt4 = (float4*)(ltile + tid * TPAD);
        float4* st4 = (float4*)(stile + tid * TPAD);
        float4* dt4 = (float4*)(dtile + tid * TPAD);
        lt4[0] = make_float4(nl_[0], nl_[1], nl_[2], nl_[3]);
        lt4[1] = make_float4(nl_[4], nl_[5], nl_[6], nl_[7]);
        st4[0] = make_float4(st0, sbuf[1], sbuf[2], sbuf[3]);   // col 24 repeats init_seas[:,0]
        st4[1] = make_float4(sbuf[4], sbuf[5], sbuf[6], sbuf[7]);
        dt4[0] = make_float4(dt_[0], dt_[1], dt_[2], dt_[3]);
        dt4[1] = make_float4(dt_[4], dt_[5], dt_[6], dt_[7]);
        __syncwarp();

        #pragma unroll
        for (int j = 0; j < 2; j++) {
            const int fq = tid + 32 * j;
            const int r  = fq >> 1, qd = fq & 1;
            const int grow = s0 + r;
            ((float4*)(gl + (size_t)grow * LEVW))[qd] =
                ((const float4*)(ltile + r * TPAD))[qd];
            ((float4*)(gs + (size_t)grow * SEAW + SEASK))[qd] =
                ((const float4*)(stile + r * TPAD))[qd];
        }
        #pragma unroll
        for (int j = 0; j < 8; j++) {
            const int i = tid + 32 * j;
            const int r = i >> 3, k = i & 7;
            if (k >= 1)
                gd[(size_t)(s0 + r) * LOGW + (k - 1)] = dtile[r * TPAD + k];
        }
        __syncwarp();
    }

    // ---- 63 steady chunks: pos0 pattern 8,16,0 repeating (period 3) ----
    #pragma unroll 1
    for (int i = 0; i < 21; i++) {
        const int c = 3 * i + 1;
        steady_chunk< 8>(c,     tid, s0, a, oma, lev, llev, sbuf,
                         ya0, ya1, yb0, yb1, ynext, gl, gs, gd, ltile, stile, dtile);
        steady_chunk<16>(c + 1, tid, s0, a, oma, lev, llev, sbuf,
                         ya0, ya1, yb0, yb1, ynext, gl, gs, gd, ltile, stile, dtile);
        steady_chunk< 0>(c + 2, tid, s0, a, oma, lev, llev, sbuf,
                         ya0, ya1, yb0, yb1, ynext, gl, gs, gd, ltile, stile, dtile);
    }
}

extern "C" void kernel_launch(void* const* d_in, const int* in_sizes, int n_in,
                              void* d_out, int out_size)
{
    const float* y         = (const float*)d_in[0];
    const int*   idxs      = (const int*)  d_in[1];
    const float* lev_sms   = (const float*)d_in[2];
    const float* init_seas = (const float*)d_in[4];  // d_in[3] unused (reference quirk)
    float* out = (float*)d_out;

    es_fwd_kernel<<<NS / BLOCK, BLOCK>>>(y, idxs, lev_sms, init_seas, out);
}

// round 4
// speedup vs baseline: 1.5518x; 1.5518x over previous
#include <cuda_runtime.h>

#define NS      32768
#define NT      512
#define SEASK   24
#define LEVW    512
#define SEAW    536
#define LOGW    511

#define BLOCK   32
#define NPER    21          // steady periods of 24 steps, starting at t=8
#define RSTRIDE 28          // smem tile row stride (floats); 28 = -4 mod 32 -> conflict-free .128
#define Y0S     12          // chunk-0 y buffer row stride

__device__ __forceinline__ unsigned smem_u32(const void* p) {
    return (unsigned)__cvta_generic_to_shared(p);
}
__device__ __forceinline__ void cp16(unsigned dst, const void* src) {
    asm volatile("cp.async.cg.shared.global [%0], [%1], 16;\n" :: "r"(dst), "l"(src) : "memory");
}
__device__ __forceinline__ void cp_commit() {
    asm volatile("cp.async.commit_group;\n" ::: "memory");
}
template<int N> __device__ __forceinline__ void cp_wait() {
    asm volatile("cp.async.wait_group %0;\n" :: "n"(N) : "memory");
}

// One 8-step chunk; POS0 compile-time => seasonal state fully register-resident.
// Within a chunk (8 < 24) every seasonal slot is read (value from >=24 steps ago)
// before being rewritten, so batching the reads first is exact.
template<int POS0>
__device__ __forceinline__ void chunk8(
    const float* __restrict__ ysm,          // this chunk's 8 y values (smem)
    float* __restrict__ lt, float* __restrict__ st, float* __restrict__ dt,
    float a, float oma, float& lev, float& llev, float (&sbuf)[SEASK])
{
    const float4 v0 = *(const float4*)(ysm);
    const float4 v1 = *(const float4*)(ysm + 4);
    float yt[8] = {v0.x, v0.y, v0.z, v0.w, v1.x, v1.y, v1.z, v1.w};
    float q_[8], os_[8], nl_[8], dt_[8];

    #pragma unroll
    for (int k = 0; k < 8; k++) {
        const float sv = sbuf[POS0 + k];
        q_[k]  = a * __fdividef(yt[k], sv);
        os_[k] = oma * sv;
    }
    #pragma unroll
    for (int k = 0; k < 8; k++) { nl_[k] = fmaf(oma, lev, q_[k]); lev = nl_[k]; }
    #pragma unroll
    for (int k = 0; k < 8; k++)
        sbuf[POS0 + k] = fmaf(a, __fdividef(yt[k], nl_[k]), os_[k]);
    #pragma unroll
    for (int k = 0; k < 8; k++) {
        const float ll = __logf(nl_[k]);
        dt_[k] = ll - llev; llev = ll;
    }

    *(float4*)(lt)     = make_float4(nl_[0], nl_[1], nl_[2], nl_[3]);
    *(float4*)(lt + 4) = make_float4(nl_[4], nl_[5], nl_[6], nl_[7]);
    *(float4*)(st)     = make_float4(sbuf[POS0+0], sbuf[POS0+1], sbuf[POS0+2], sbuf[POS0+3]);
    *(float4*)(st + 4) = make_float4(sbuf[POS0+4], sbuf[POS0+5], sbuf[POS0+6], sbuf[POS0+7]);
    *(float4*)(dt)     = make_float4(dt_[0], dt_[1], dt_[2], dt_[3]);
    *(float4*)(dt + 4) = make_float4(dt_[4], dt_[5], dt_[6], dt_[7]);
}

__global__ __launch_bounds__(BLOCK) void es_fwd_kernel(
    const float* __restrict__ y,
    const int*   __restrict__ idxs,
    const float* __restrict__ lev_sms_p,
    const float* __restrict__ init_seas_p,
    float* __restrict__ out)
{
    __shared__ __align__(16) float ybuf[2][BLOCK * RSTRIDE];  // period y staging (double-buffered)
    __shared__ __align__(16) float y0buf[BLOCK * Y0S];        // chunk-0 y staging
    __shared__ __align__(16) float ltile[BLOCK * RSTRIDE];
    __shared__ __align__(16) float stile[BLOCK * RSTRIDE];
    __shared__ __align__(16) float dtile[BLOCK * RSTRIDE];

    const int tid = threadIdx.x;
    const int s0  = blockIdx.x * BLOCK;
    const int s   = s0 + tid;

    float* gl = out;
    float* gs = out + (size_t)NS * LEVW;
    float* gd = gs  + (size_t)NS * SEAW;

    const int idx = idxs[s];
    // reference derives BOTH smoothing params from lev_sms (its own quirk)
    const float a   = 1.0f / (1.0f + __expf(-lev_sms_p[idx]));
    const float oma = 1.0f - a;

    // ---- launch async y loads first so they fly under the init work ----
    const char* ybase = (const char*)(y + (size_t)s0 * NT);
    unsigned goff[6], soff[6];
    #pragma unroll
    for (int j = 0; j < 6; j++) {
        const int f = tid + 32 * j;
        const int row = f / 6, col = f % 6;            // 24 floats (6 x float4) per row
        goff[j] = row * (NT * 4) + col * 16;
        soff[j] = row * (RSTRIDE * 4) + col * 16;
    }
    // chunk 0: y[:, 0:8)  (64 float4)
    #pragma unroll
    for (int j = 0; j < 2; j++) {
        const int f = tid + 32 * j;
        const int row = f / 2, col = f % 2;
        cp16(smem_u32(y0buf) + row * (Y0S * 4) + col * 16,
             ybase + row * (NT * 4) + col * 16);
    }
    cp_commit();
    // period 0: y[:, 8:32)
    const unsigned ysb[2] = { smem_u32(ybuf[0]), smem_u32(ybuf[1]) };
    #pragma unroll
    for (int j = 0; j < 6; j++) cp16(ysb[0] + soff[j], ybase + 32 + goff[j]);
    cp_commit();

    // ---- seasonal state in registers; emit seas cols 0..23 ----
    float sbuf[SEASK];
    {
        const float4* isr = (const float4*)(init_seas_p + (size_t)idx * SEASK);
        float4* gsr = (float4*)(gs + (size_t)s * SEAW);
        #pragma unroll
        for (int qd = 0; qd < 6; qd++) {
            float4 v = isr[qd];
            v.x = __expf(v.x); v.y = __expf(v.y); v.z = __expf(v.z); v.w = __expf(v.w);
            sbuf[4*qd+0] = v.x; sbuf[4*qd+1] = v.y;
            sbuf[4*qd+2] = v.z; sbuf[4*qd+3] = v.w;
            gsr[qd] = v;
        }
    }

    float lev, llev;

    // ================= chunk 0 (steps 0..7, step 0 special) =================
    cp_wait<1>();        // chunk-0 group done; period-0 group may still fly
    __syncwarp();
    {
        const float4 v0 = *(const float4*)(y0buf + tid * Y0S);
        const float4 v1 = *(const float4*)(y0buf + tid * Y0S + 4);
        float yt[8] = {v0.x, v0.y, v0.z, v0.w, v1.x, v1.y, v1.z, v1.w};
        float q_[8], os_[8], nl_[8], dt_[8];

        const float st0 = sbuf[0];
        lev  = __fdividef(yt[0], st0);
        llev = __logf(lev);
        nl_[0] = lev; dt_[0] = 0.0f;

        #pragma unroll
        for (int k = 1; k < 8; k++) {
            const float sv = sbuf[k];
            q_[k]  = a * __fdividef(yt[k], sv);
            os_[k] = oma * sv;
        }
        #pragma unroll
        for (int k = 1; k < 8; k++) { nl_[k] = fmaf(oma, lev, q_[k]); lev = nl_[k]; }
        #pragma unroll
        for (int k = 1; k < 8; k++)
            sbuf[k] = fmaf(a, __fdividef(yt[k], nl_[k]), os_[k]);
        #pragma unroll
        for (int k = 1; k < 8; k++) {
            const float ll = __logf(nl_[k]);
            dt_[k] = ll - llev; llev = ll;
        }

        float* lt = ltile + tid * RSTRIDE;
        float* st = stile + tid * RSTRIDE;
        float* dt = dtile + tid * RSTRIDE;
        *(float4*)(lt)     = make_float4(nl_[0], nl_[1], nl_[2], nl_[3]);
        *(float4*)(lt + 4) = make_float4(nl_[4], nl_[5], nl_[6], nl_[7]);
        *(float4*)(st)     = make_float4(st0, sbuf[1], sbuf[2], sbuf[3]);  // col 24 = init_seas[:,0]
        *(float4*)(st + 4) = make_float4(sbuf[4], sbuf[5], sbuf[6], sbuf[7]);
        *(float4*)(dt)     = make_float4(dt_[0], dt_[1], dt_[2], dt_[3]);
        *(float4*)(dt + 4) = make_float4(dt_[4], dt_[5], dt_[6], dt_[7]);
        __syncwarp();

        // writeback: levels cols 0..7, seas cols 24..31, logd cols 0..6
        #pragma unroll
        for (int j = 0; j < 2; j++) {
            const int f = tid + 32 * j;
            const int row = f / 2, qd = f % 2;
            *(float4*)(gl + (size_t)(s0 + row) * LEVW + qd * 4) =
                ((const float4*)(ltile + row * RSTRIDE))[qd];
            *(float4*)(gs + (size_t)(s0 + row) * SEAW + SEASK + qd * 4) =
                ((const float4*)(stile + row * RSTRIDE))[qd];
        }
        #pragma unroll
        for (int j = 0; j < 7; j++) {
            const int i = tid + 32 * j;
            const int row = i / 7, k = i % 7;
            gd[(size_t)(s0 + row) * LOGW + k] = dtile[row * RSTRIDE + 1 + k];
        }
        __syncwarp();
    }

    // ================= 21 steady periods of 24 steps =================
    #pragma unroll 1
    for (int p = 0; p < NPER; p++) {
        // prefetch next period (depth-1 pipeline), then wait for current
        if (p + 1 < NPER) {
            const char* yb = ybase + 32 + (size_t)(p + 1) * 96;
            const unsigned d = ysb[(p + 1) & 1];
            #pragma unroll
            for (int j = 0; j < 6; j++) cp16(d + soff[j], yb + goff[j]);
            cp_commit();
            cp_wait<1>();
        } else {
            cp_wait<0>();
        }
        __syncwarp();

        const float* ysm = ybuf[p & 1] + tid * RSTRIDE;
        float* lt = ltile + tid * RSTRIDE;
        float* st = stile + tid * RSTRIDE;
        float* dt = dtile + tid * RSTRIDE;

        chunk8< 8>(ysm + 0,  lt + 0,  st + 0,  dt + 0,  a, oma, lev, llev, sbuf);
        chunk8<16>(ysm + 8,  lt + 8,  st + 8,  dt + 8,  a, oma, lev, llev, sbuf);
        chunk8< 0>(ysm + 16, lt + 16, st + 16, dt + 16, a, oma, lev, llev, sbuf);
        __syncwarp();

        // writeback: 24 cols per row, row=f/6 mapping (~6 lines per instruction)
        const int tp = 8 + 24 * p;
        #pragma unroll
        for (int j = 0; j < 6; j++) {
            const int f = tid + 32 * j;
            const int row = f / 6, c4 = f % 6;
            const int grow = s0 + row;
            *(float4*)(gl + (size_t)grow * LEVW + tp + c4 * 4) =
                *(const float4*)(ltile + row * RSTRIDE + c4 * 4);
            *(float4*)(gs + (size_t)grow * SEAW + tp + SEASK + c4 * 4) =
                *(const float4*)(stile + row * RSTRIDE + c4 * 4);
        }
        #pragma unroll
        for (int j = 0; j < 24; j++) {
            const int i = tid + 32 * j;
            const int row = i / 24, k = i % 24;
            gd[(size_t)(s0 + row) * LOGW + tp - 1 + k] = dtile[row * RSTRIDE + k];
        }
        __syncwarp();
    }
}

extern "C" void kernel_launch(void* const* d_in, const int* in_sizes, int n_in,
                              void* d_out, int out_size)
{
    const float* y         = (const float*)d_in[0];
    const int*   idxs      = (const int*)  d_in[1];
    const float* lev_sms   = (const float*)d_in[2];
    const float* init_seas = (const float*)d_in[4];  // d_in[3] unused (reference quirk)
    float* out = (float*)d_out;

    es_fwd_kernel<<<NS / BLOCK, BLOCK>>>(y, idxs, lev_sms, init_seas, out);
}